// round 5
// baseline (speedup 1.0000x reference)
#include <cuda_runtime.h>

#define EPSF 1e-6f

#define NP     1024
#define DIM    768
#define QK_LD  6144   /* q|k combined columns: 2 * 48 * 64 */
#define V_LD   3072

// Scratch (device globals: allowed; no runtime allocation)
__device__ float g_qkbuf[NP * QK_LD];          // feature-mapped q|k, [n, col]
__device__ float g_qk2 [NP * QK_LD];           // q|k after graph mix
__device__ float g_v   [NP * V_LD];            // v, [n, col]
__device__ float g_attn[4 * NP * DIM];         // attention output [B*N, C]

// ---------------------------------------------------------------------------
// Generic 128x128x8 SGEMM, 256 threads, 8x8 register tile.
// TRANSA=false: A row-major [M,K].  TRANSA=true: A is [K,M] (i.e. op(A)=A^T).
// EPI 0: qkv scatter+relu+eps   EPI 1: C = F + 0.1*acc   EPI 2: C = acc + bias
// ---------------------------------------------------------------------------
template<bool TRANSA, int EPI>
__global__ __launch_bounds__(256)
void sgemm_kernel(const float* __restrict__ A, const float* __restrict__ B,
                  float* __restrict__ C, const float* __restrict__ bias,
                  int M, int N, int K, int lda, int ldb)
{
    __shared__ __align__(16) float As[8][128];
    __shared__ __align__(16) float Bs[8][128];

    const int tid = threadIdx.x;
    const int tr  = tid >> 4;      // 0..15
    const int tc  = tid & 15;      // 0..15
    const int m_base = blockIdx.y * 128;
    const int n_base = blockIdx.x * 128;

    float acc[8][8];
    #pragma unroll
    for (int i = 0; i < 8; i++)
        #pragma unroll
        for (int j = 0; j < 8; j++) acc[i][j] = 0.f;

    for (int k0 = 0; k0 < K; k0 += 8) {
        if (!TRANSA) {
            const int am = tid >> 1, ak = (tid & 1) * 4;
            float4 a = *(const float4*)&A[(size_t)(m_base + am) * lda + k0 + ak];
            As[ak+0][am] = a.x; As[ak+1][am] = a.y;
            As[ak+2][am] = a.z; As[ak+3][am] = a.w;
        } else {
            const int ak = tid >> 5, am4 = (tid & 31) * 4;
            *(float4*)&As[ak][am4] =
                *(const float4*)&A[(size_t)(k0 + ak) * lda + m_base + am4];
        }
        {
            const int bk = tid >> 5, bn4 = (tid & 31) * 4;
            *(float4*)&Bs[bk][bn4] =
                *(const float4*)&B[(size_t)(k0 + bk) * ldb + n_base + bn4];
        }
        __syncthreads();
        #pragma unroll
        for (int k = 0; k < 8; k++) {
            float a[8], b[8];
            *(float4*)&a[0] = *(float4*)&As[k][tr*8];
            *(float4*)&a[4] = *(float4*)&As[k][tr*8+4];
            *(float4*)&b[0] = *(float4*)&Bs[k][tc*8];
            *(float4*)&b[4] = *(float4*)&Bs[k][tc*8+4];
            #pragma unroll
            for (int i = 0; i < 8; i++)
                #pragma unroll
                for (int j = 0; j < 8; j++)
                    acc[i][j] += a[i] * b[j];
        }
        __syncthreads();
    }

    if (EPI == 0) {
        // QKV scatter. Row R = b*1024 + n.  Column c < 768: q, <1536: k, else v.
        // (b*12 + c/64)*64 + c%64 == b*768 + c, so writes stay contiguous.
        #pragma unroll
        for (int i = 0; i < 8; i++) {
            const int row = m_base + tr*8 + i;
            const int bb  = row >> 10;
            const int n   = row & 1023;
            #pragma unroll
            for (int jj = 0; jj < 2; jj++) {
                const int col = n_base + tc*8 + jj*4;
                float4 v = make_float4(acc[i][jj*4+0], acc[i][jj*4+1],
                                       acc[i][jj*4+2], acc[i][jj*4+3]);
                if (col < 768) {
                    v.x = fmaxf(v.x, 0.f) + EPSF; v.y = fmaxf(v.y, 0.f) + EPSF;
                    v.z = fmaxf(v.z, 0.f) + EPSF; v.w = fmaxf(v.w, 0.f) + EPSF;
                    *(float4*)&g_qkbuf[(size_t)n * QK_LD + bb*768 + col] = v;
                } else if (col < 1536) {
                    v.x = fmaxf(v.x, 0.f) + EPSF; v.y = fmaxf(v.y, 0.f) + EPSF;
                    v.z = fmaxf(v.z, 0.f) + EPSF; v.w = fmaxf(v.w, 0.f) + EPSF;
                    *(float4*)&g_qkbuf[(size_t)n * QK_LD + 3072 + bb*768 + (col-768)] = v;
                } else {
                    *(float4*)&g_v[(size_t)n * V_LD + bb*768 + (col-1536)] = v;
                }
            }
        }
    } else if (EPI == 1) {
        // C = F + 0.1 * (mask^T @ F),  F = g_qkbuf, N == QK_LD
        #pragma unroll
        for (int i = 0; i < 8; i++) {
            const int row = m_base + tr*8 + i;
            #pragma unroll
            for (int jj = 0; jj < 2; jj++) {
                const int col = n_base + tc*8 + jj*4;
                float4 f = *(const float4*)&g_qkbuf[(size_t)row * N + col];
                float4 o = make_float4(f.x + 0.1f*acc[i][jj*4+0],
                                       f.y + 0.1f*acc[i][jj*4+1],
                                       f.z + 0.1f*acc[i][jj*4+2],
                                       f.w + 0.1f*acc[i][jj*4+3]);
                *(float4*)&C[(size_t)row * N + col] = o;
            }
        }
    } else {
        // C = acc + bias
        #pragma unroll
        for (int i = 0; i < 8; i++) {
            const int row = m_base + tr*8 + i;
            #pragma unroll
            for (int jj = 0; jj < 2; jj++) {
                const int col = n_base + tc*8 + jj*4;
                float4 bv = *(const float4*)&bias[col];
                float4 o = make_float4(acc[i][jj*4+0] + bv.x,
                                       acc[i][jj*4+1] + bv.y,
                                       acc[i][jj*4+2] + bv.z,
                                       acc[i][jj*4+3] + bv.w);
                *(float4*)&C[(size_t)row * N + col] = o;
            }
        }
    }
}

// ---------------------------------------------------------------------------
// Masked linear attention, flash-style.
// grid = (16 n-tiles, 48 bh). block = 256 threads, 64x64 output tile.
// out[n,d] = (sum_m mask[n,m] (q_n . k_m) v[m,d]) / (sum_m mask[n,m] (q_n . k_m) + eps)
// ---------------------------------------------------------------------------
#define ATTN_SMEM ((4 * 64 * 68 + 64 * 64) * 4)

__global__ __launch_bounds__(256)
void attn_kernel(const float* __restrict__ mask)
{
    extern __shared__ float sm[];
    float* Qs = sm;                 // [64][68]  Qs[d][n]
    float* Ks = Qs + 64*68;         // [64][68]  Ks[d][m]
    float* Ms = Ks + 64*68;         // [64][68]  Ms[n][m]
    float* Ps = Ms + 64*68;         // [64][68]  Ps[m][n]  (masked scores, transposed)
    float* Vs = Ps + 64*68;         // [64][64]  Vs[m][d]

    const int tid = threadIdx.x;
    const int tr  = tid >> 4;       // n sub-tile (4 rows)
    const int tc  = tid & 15;       // d / m sub-tile (4 cols)
    const int n0  = blockIdx.x * 64;
    const int bh  = blockIdx.y;
    const int qoff = bh * 64;

    // Load Q tile once, transposed to d-major
    #pragma unroll
    for (int i = 0; i < 4; i++) {
        const int l = tid + i * 256;
        const int n = l >> 4, d4 = (l & 15) * 4;
        float4 v = *(const float4*)&g_qk2[(size_t)(n0 + n) * QK_LD + qoff + d4];
        Qs[(d4+0)*68 + n] = v.x; Qs[(d4+1)*68 + n] = v.y;
        Qs[(d4+2)*68 + n] = v.z; Qs[(d4+3)*68 + n] = v.w;
    }

    float acc[4][4] = {};
    float rs[4] = {};

    for (int mt = 0; mt < 16; mt++) {
        const int m0 = mt * 64;
        __syncthreads();   // previous iteration fully consumed (also covers Q load)

        #pragma unroll
        for (int i = 0; i < 4; i++) {
            const int l = tid + i * 256;
            const int r = l >> 4, c4 = (l & 15) * 4;
            float4 kv = *(const float4*)&g_qk2[(size_t)(m0 + r) * QK_LD + 3072 + qoff + c4];
            Ks[(c4+0)*68 + r] = kv.x; Ks[(c4+1)*68 + r] = kv.y;
            Ks[(c4+2)*68 + r] = kv.z; Ks[(c4+3)*68 + r] = kv.w;
            *(float4*)&Vs[r*64 + c4] =
                *(const float4*)&g_v[(size_t)(m0 + r) * V_LD + qoff + c4];
            *(float4*)&Ms[r*68 + c4] =
                *(const float4*)&mask[(size_t)(n0 + r) * 1024 + m0 + c4];
        }
        __syncthreads();

        // S = Q K^T for this thread's 4n x 4m
        float s[4][4] = {};
        #pragma unroll 8
        for (int d = 0; d < 64; d++) {
            float4 q = *(const float4*)&Qs[d*68 + tr*4];
            float4 k = *(const float4*)&Ks[d*68 + tc*4];
            const float qa[4] = {q.x, q.y, q.z, q.w};
            const float ka[4] = {k.x, k.y, k.z, k.w};
            #pragma unroll
            for (int i = 0; i < 4; i++)
                #pragma unroll
                for (int j = 0; j < 4; j++)
                    s[i][j] += qa[i] * ka[j];
        }
        // Apply mask, publish P^T
        #pragma unroll
        for (int i = 0; i < 4; i++)
            #pragma unroll
            for (int j = 0; j < 4; j++)
                Ps[(tc*4+j)*68 + tr*4+i] = s[i][j] * Ms[(tr*4+i)*68 + tc*4+j];
        __syncthreads();

        // acc += P V ; rowsum rides along for free
        #pragma unroll 8
        for (int m = 0; m < 64; m++) {
            float4 p = *(const float4*)&Ps[m*68 + tr*4];
            float4 v = *(const float4*)&Vs[m*64 + tc*4];
            const float pa[4] = {p.x, p.y, p.z, p.w};
            const float va[4] = {v.x, v.y, v.z, v.w};
            #pragma unroll
            for (int i = 0; i < 4; i++) {
                rs[i] += pa[i];
                #pragma unroll
                for (int j = 0; j < 4; j++)
                    acc[i][j] += pa[i] * va[j];
            }
        }
    }

    const int b = bh / 12, h = bh % 12;
    #pragma unroll
    for (int i = 0; i < 4; i++) {
        const float z = 1.f / (rs[i] + EPSF);
        const size_t row = (size_t)(b * 1024 + n0 + tr*4 + i);
        float4 o = make_float4(acc[i][0]*z, acc[i][1]*z, acc[i][2]*z, acc[i][3]*z);
        *(float4*)&g_attn[row * 768 + h*64 + tc*4] = o;
    }
}

// ---------------------------------------------------------------------------

extern "C" void kernel_launch(void* const* d_in, const int* in_sizes, int n_in,
                              void* d_out, int out_size)
{
    (void)in_sizes; (void)n_in; (void)out_size;
    const float* x     = (const float*)d_in[0];   // [4,1024,768]
    const float* W_qkv = (const float*)d_in[1];   // [768,2304]
    const float* W_out = (const float*)d_in[2];   // [768,768]
    const float* b_out = (const float*)d_in[3];   // [768]
    const float* mask  = (const float*)d_in[4];   // [1024,1024]
    float* out = (float*)d_out;                   // [4,1024,768]

    // Scratch symbol addresses (host API, no allocation; deterministic)
    float *p_qkbuf = nullptr, *p_qk2 = nullptr, *p_attn = nullptr;
    cudaGetSymbolAddress((void**)&p_qkbuf, g_qkbuf);
    cudaGetSymbolAddress((void**)&p_qk2,  g_qk2);
    cudaGetSymbolAddress((void**)&p_attn, g_attn);

    cudaFuncSetAttribute(attn_kernel,
                         cudaFuncAttributeMaxDynamicSharedMemorySize, ATTN_SMEM);

    dim3 blk(256);

    // 1) QKV GEMM: [4096,768] @ [768,2304] -> relu/eps scatter into g_qkbuf / g_v
    sgemm_kernel<false, 0><<<dim3(2304/128, 4096/128), blk>>>(
        x, W_qkv, nullptr, nullptr, 4096, 2304, 768, 768, 2304);

    // 2) Graph mix: g_qk2 = F + 0.1 * (mask^T @ F), F = g_qkbuf [1024,6144]
    sgemm_kernel<true, 1><<<dim3(6144/128, 1024/128), blk>>>(
        mask, p_qkbuf, p_qk2, nullptr, 1024, 6144, 1024, 1024, QK_LD);

    // 3) Masked linear attention -> g_attn [4096,768]
    attn_kernel<<<dim3(16, 48), blk, ATTN_SMEM>>>(mask);

    // 4) Output projection: [4096,768] @ [768,768] + b_out -> d_out
    sgemm_kernel<false, 2><<<dim3(768/128, 4096/128), blk>>>(
        p_attn, W_out, out, b_out, 4096, 768, 768, 768, 768);
}

// round 6
// speedup vs baseline: 1.0546x; 1.0546x over previous
#include <cuda_runtime.h>

#define EPSF 1e-6f

#define NP     1024
#define DIM    768
#define QK_LD  6144   /* q|k combined columns: 2 * 48 * 64 */
#define V_LD   3072

typedef unsigned long long u64;

// Packed f32x2 helpers (Blackwell sm_103a): the ONLY way to get FFMA2.
#define FFMA2(d, a, b) \
    asm volatile("fma.rn.f32x2 %0, %1, %2, %0;" : "+l"(d) : "l"(a), "l"(b))
#define DUP2(d, s) \
    asm("mov.b64 %0, {%1, %1};" : "=l"(d) : "r"(__float_as_uint(s)))
#define UNPK2(lo, hi, d) \
    asm("mov.b64 {%0, %1}, %2;" : "=f"(lo), "=f"(hi) : "l"(d))

// Scratch (device globals: allowed; no runtime allocation)
__device__ float g_qkbuf[NP * QK_LD];          // feature-mapped q|k, [n, col]
__device__ float g_qk2 [NP * QK_LD];           // q|k after graph mix
__device__ float g_v   [NP * V_LD];            // v, [n, col]
__device__ float g_attn[4 * NP * DIM];         // attention output [B*N, C]

// ---------------------------------------------------------------------------
// 128x128x16 SGEMM, 256 threads, 8x8 register tile, FFMA2 inner loop.
// TRANSA=false: A row-major [M,K].  TRANSA=true: op(A)=A^T with A [K,M].
// EPI 0: qkv scatter+relu+eps   EPI 1: C = F + 0.1*acc   EPI 2: C = acc + bias
// ---------------------------------------------------------------------------
template<bool TRANSA, int EPI>
__global__ __launch_bounds__(256, 2)
void sgemm_kernel(const float* __restrict__ A, const float* __restrict__ B,
                  float* __restrict__ C, const float* __restrict__ bias,
                  int M, int N, int K, int lda, int ldb)
{
    __shared__ __align__(16) float As[16][128];
    __shared__ __align__(16) float Bs[16][128];

    const int tid = threadIdx.x;
    const int tr  = tid >> 4;      // 0..15
    const int tc  = tid & 15;      // 0..15
    const int m_base = blockIdx.y * 128;
    const int n_base = blockIdx.x * 128;

    u64 acc2[8][4];                // acc2[i][j2] = (acc[i][2j2], acc[i][2j2+1])
    #pragma unroll
    for (int i = 0; i < 8; i++)
        #pragma unroll
        for (int j = 0; j < 4; j++) acc2[i][j] = 0ull;

    for (int k0 = 0; k0 < K; k0 += 16) {
        if (!TRANSA) {
            const int am = tid >> 1, ak = (tid & 1) * 8;
            float4 a0 = *(const float4*)&A[(size_t)(m_base + am) * lda + k0 + ak];
            float4 a1 = *(const float4*)&A[(size_t)(m_base + am) * lda + k0 + ak + 4];
            As[ak+0][am] = a0.x; As[ak+1][am] = a0.y;
            As[ak+2][am] = a0.z; As[ak+3][am] = a0.w;
            As[ak+4][am] = a1.x; As[ak+5][am] = a1.y;
            As[ak+6][am] = a1.z; As[ak+7][am] = a1.w;
        } else {
            const int ak = tid >> 4, am8 = (tid & 15) * 8;
            *(float4*)&As[ak][am8] =
                *(const float4*)&A[(size_t)(k0 + ak) * lda + m_base + am8];
            *(float4*)&As[ak][am8+4] =
                *(const float4*)&A[(size_t)(k0 + ak) * lda + m_base + am8 + 4];
        }
        {
            const int bk = tid >> 4, bn8 = (tid & 15) * 8;
            *(float4*)&Bs[bk][bn8] =
                *(const float4*)&B[(size_t)(k0 + bk) * ldb + n_base + bn8];
            *(float4*)&Bs[bk][bn8+4] =
                *(const float4*)&B[(size_t)(k0 + bk) * ldb + n_base + bn8 + 4];
        }
        __syncthreads();
        #pragma unroll
        for (int k = 0; k < 16; k++) {
            u64 b2[4];
            b2[0] = *(const u64*)&Bs[k][tc*8+0];
            b2[1] = *(const u64*)&Bs[k][tc*8+2];
            b2[2] = *(const u64*)&Bs[k][tc*8+4];
            b2[3] = *(const u64*)&Bs[k][tc*8+6];
            float4 a0 = *(const float4*)&As[k][tr*8];
            float4 a1 = *(const float4*)&As[k][tr*8+4];
            const float av[8] = {a0.x, a0.y, a0.z, a0.w, a1.x, a1.y, a1.z, a1.w};
            #pragma unroll
            for (int i = 0; i < 8; i++) {
                u64 ad; DUP2(ad, av[i]);
                #pragma unroll
                for (int j = 0; j < 4; j++)
                    FFMA2(acc2[i][j], ad, b2[j]);
            }
        }
        __syncthreads();
    }

    // Unpack accumulators
    float acc[8][8];
    #pragma unroll
    for (int i = 0; i < 8; i++)
        #pragma unroll
        for (int j = 0; j < 4; j++)
            UNPK2(acc[i][2*j], acc[i][2*j+1], acc2[i][j]);

    if (EPI == 0) {
        // QKV scatter. Row R = b*1024 + n.  Column c < 768: q, <1536: k, else v.
        // (b*12 + c/64)*64 + c%64 == b*768 + c, so writes stay contiguous.
        #pragma unroll
        for (int i = 0; i < 8; i++) {
            const int row = m_base + tr*8 + i;
            const int bb  = row >> 10;
            const int n   = row & 1023;
            #pragma unroll
            for (int jj = 0; jj < 2; jj++) {
                const int col = n_base + tc*8 + jj*4;
                float4 v = make_float4(acc[i][jj*4+0], acc[i][jj*4+1],
                                       acc[i][jj*4+2], acc[i][jj*4+3]);
                if (col < 768) {
                    v.x = fmaxf(v.x, 0.f) + EPSF; v.y = fmaxf(v.y, 0.f) + EPSF;
                    v.z = fmaxf(v.z, 0.f) + EPSF; v.w = fmaxf(v.w, 0.f) + EPSF;
                    *(float4*)&g_qkbuf[(size_t)n * QK_LD + bb*768 + col] = v;
                } else if (col < 1536) {
                    v.x = fmaxf(v.x, 0.f) + EPSF; v.y = fmaxf(v.y, 0.f) + EPSF;
                    v.z = fmaxf(v.z, 0.f) + EPSF; v.w = fmaxf(v.w, 0.f) + EPSF;
                    *(float4*)&g_qkbuf[(size_t)n * QK_LD + 3072 + bb*768 + (col-768)] = v;
                } else {
                    *(float4*)&g_v[(size_t)n * V_LD + bb*768 + (col-1536)] = v;
                }
            }
        }
    } else if (EPI == 1) {
        // C = F + 0.1 * (mask^T @ F),  F = g_qkbuf, N == QK_LD
        #pragma unroll
        for (int i = 0; i < 8; i++) {
            const int row = m_base + tr*8 + i;
            #pragma unroll
            for (int jj = 0; jj < 2; jj++) {
                const int col = n_base + tc*8 + jj*4;
                float4 f = *(const float4*)&g_qkbuf[(size_t)row * N + col];
                float4 o = make_float4(f.x + 0.1f*acc[i][jj*4+0],
                                       f.y + 0.1f*acc[i][jj*4+1],
                                       f.z + 0.1f*acc[i][jj*4+2],
                                       f.w + 0.1f*acc[i][jj*4+3]);
                *(float4*)&C[(size_t)row * N + col] = o;
            }
        }
    } else {
        // C = acc + bias
        #pragma unroll
        for (int i = 0; i < 8; i++) {
            const int row = m_base + tr*8 + i;
            #pragma unroll
            for (int jj = 0; jj < 2; jj++) {
                const int col = n_base + tc*8 + jj*4;
                float4 bv = *(const float4*)&bias[col];
                float4 o = make_float4(acc[i][jj*4+0] + bv.x,
                                       acc[i][jj*4+1] + bv.y,
                                       acc[i][jj*4+2] + bv.z,
                                       acc[i][jj*4+3] + bv.w);
                *(float4*)&C[(size_t)row * N + col] = o;
            }
        }
    }
}

// ---------------------------------------------------------------------------
// Masked linear attention, flash-style, FFMA2 inner loops.
// grid = (16 n-tiles, 48 bh). block = 256 threads, 64x64 output tile.
// out[n,d] = (sum_m mask[n,m] (q_n . k_m) v[m,d]) / (sum_m mask[n,m] (q_n . k_m) + eps)
// ---------------------------------------------------------------------------
#define ATTN_SMEM ((4 * 64 * 68 + 64 * 64) * 4)

__global__ __launch_bounds__(256)
void attn_kernel(const float* __restrict__ mask)
{
    extern __shared__ float sm[];
    float* Qs = sm;                 // [64][68]  Qs[d][n]
    float* Ks = Qs + 64*68;         // [64][68]  Ks[d][m]
    float* Ms = Ks + 64*68;         // [64][68]  Ms[n][m]
    float* Ps = Ms + 64*68;         // [64][68]  Ps[m][n]  (masked scores, transposed)
    float* Vs = Ps + 64*68;         // [64][64]  Vs[m][d]

    const int tid = threadIdx.x;
    const int tr  = tid >> 4;       // n sub-tile (4 rows)
    const int tc  = tid & 15;       // d / m sub-tile (4 cols)
    const int n0  = blockIdx.x * 64;
    const int bh  = blockIdx.y;
    const int qoff = bh * 64;

    // Load Q tile once, transposed to d-major
    #pragma unroll
    for (int i = 0; i < 4; i++) {
        const int l = tid + i * 256;
        const int n = l >> 4, d4 = (l & 15) * 4;
        float4 v = *(const float4*)&g_qk2[(size_t)(n0 + n) * QK_LD + qoff + d4];
        Qs[(d4+0)*68 + n] = v.x; Qs[(d4+1)*68 + n] = v.y;
        Qs[(d4+2)*68 + n] = v.z; Qs[(d4+3)*68 + n] = v.w;
    }

    u64 acc2[4][2];                 // packed over d pairs
    #pragma unroll
    for (int i = 0; i < 4; i++) { acc2[i][0] = 0ull; acc2[i][1] = 0ull; }
    float rs[4] = {};

    for (int mt = 0; mt < 16; mt++) {
        const int m0 = mt * 64;
        __syncthreads();   // previous iteration fully consumed (also covers Q load)

        #pragma unroll
        for (int i = 0; i < 4; i++) {
            const int l = tid + i * 256;
            const int r = l >> 4, c4 = (l & 15) * 4;
            float4 kv = *(const float4*)&g_qk2[(size_t)(m0 + r) * QK_LD + 3072 + qoff + c4];
            Ks[(c4+0)*68 + r] = kv.x; Ks[(c4+1)*68 + r] = kv.y;
            Ks[(c4+2)*68 + r] = kv.z; Ks[(c4+3)*68 + r] = kv.w;
            *(float4*)&Vs[r*64 + c4] =
                *(const float4*)&g_v[(size_t)(m0 + r) * V_LD + qoff + c4];
            *(float4*)&Ms[r*68 + c4] =
                *(const float4*)&mask[(size_t)(n0 + r) * 1024 + m0 + c4];
        }
        __syncthreads();

        // S = Q K^T for this thread's 4n x 4m (packed over m)
        u64 s2[4][2];
        #pragma unroll
        for (int i = 0; i < 4; i++) { s2[i][0] = 0ull; s2[i][1] = 0ull; }
        #pragma unroll 8
        for (int d = 0; d < 64; d++) {
            float4 q = *(const float4*)&Qs[d*68 + tr*4];
            u64 k0p = *(const u64*)&Ks[d*68 + tc*4];
            u64 k1p = *(const u64*)&Ks[d*68 + tc*4 + 2];
            const float qa[4] = {q.x, q.y, q.z, q.w};
            #pragma unroll
            for (int i = 0; i < 4; i++) {
                u64 qd; DUP2(qd, qa[i]);
                FFMA2(s2[i][0], qd, k0p);
                FFMA2(s2[i][1], qd, k1p);
            }
        }
        // Apply mask, publish P^T
        #pragma unroll
        for (int i = 0; i < 4; i++) {
            float s[4];
            UNPK2(s[0], s[1], s2[i][0]);
            UNPK2(s[2], s[3], s2[i][1]);
            #pragma unroll
            for (int j = 0; j < 4; j++)
                Ps[(tc*4+j)*68 + tr*4+i] = s[j] * Ms[(tr*4+i)*68 + tc*4+j];
        }
        __syncthreads();

        // acc += P V ; rowsum rides along
        #pragma unroll 8
        for (int m = 0; m < 64; m++) {
            float4 p = *(const float4*)&Ps[m*68 + tr*4];
            u64 v0p = *(const u64*)&Vs[m*64 + tc*4];
            u64 v1p = *(const u64*)&Vs[m*64 + tc*4 + 2];
            const float pa[4] = {p.x, p.y, p.z, p.w};
            #pragma unroll
            for (int i = 0; i < 4; i++) {
                rs[i] += pa[i];
                u64 pd; DUP2(pd, pa[i]);
                FFMA2(acc2[i][0], pd, v0p);
                FFMA2(acc2[i][1], pd, v1p);
            }
        }
    }

    const int b = bh / 12, h = bh % 12;
    #pragma unroll
    for (int i = 0; i < 4; i++) {
        const float z = 1.f / (rs[i] + EPSF);
        float a[4];
        UNPK2(a[0], a[1], acc2[i][0]);
        UNPK2(a[2], a[3], acc2[i][1]);
        const size_t row = (size_t)(b * 1024 + n0 + tr*4 + i);
        float4 o = make_float4(a[0]*z, a[1]*z, a[2]*z, a[3]*z);
        *(float4*)&g_attn[row * 768 + h*64 + tc*4] = o;
    }
}

// ---------------------------------------------------------------------------

extern "C" void kernel_launch(void* const* d_in, const int* in_sizes, int n_in,
                              void* d_out, int out_size)
{
    (void)in_sizes; (void)n_in; (void)out_size;
    const float* x     = (const float*)d_in[0];   // [4,1024,768]
    const float* W_qkv = (const float*)d_in[1];   // [768,2304]
    const float* W_out = (const float*)d_in[2];   // [768,768]
    const float* b_out = (const float*)d_in[3];   // [768]
    const float* mask  = (const float*)d_in[4];   // [1024,1024]
    float* out = (float*)d_out;                   // [4,1024,768]

    // Scratch symbol addresses (host API, no allocation; deterministic)
    float *p_qkbuf = nullptr, *p_qk2 = nullptr, *p_attn = nullptr;
    cudaGetSymbolAddress((void**)&p_qkbuf, g_qkbuf);
    cudaGetSymbolAddress((void**)&p_qk2,  g_qk2);
    cudaGetSymbolAddress((void**)&p_attn, g_attn);

    cudaFuncSetAttribute(attn_kernel,
                         cudaFuncAttributeMaxDynamicSharedMemorySize, ATTN_SMEM);

    dim3 blk(256);

    // 1) QKV GEMM: [4096,768] @ [768,2304] -> relu/eps scatter into g_qkbuf / g_v
    sgemm_kernel<false, 0><<<dim3(2304/128, 4096/128), blk>>>(
        x, W_qkv, nullptr, nullptr, 4096, 2304, 768, 768, 2304);

    // 2) Graph mix: g_qk2 = F + 0.1 * (mask^T @ F), F = g_qkbuf [1024,6144]
    sgemm_kernel<true, 1><<<dim3(6144/128, 1024/128), blk>>>(
        mask, p_qkbuf, p_qk2, nullptr, 1024, 6144, 1024, 1024, QK_LD);

    // 3) Masked linear attention -> g_attn [4096,768]
    attn_kernel<<<dim3(16, 48), blk, ATTN_SMEM>>>(mask);

    // 4) Output projection: [4096,768] @ [768,768] + b_out -> d_out
    sgemm_kernel<false, 2><<<dim3(768/128, 4096/128), blk>>>(
        p_attn, W_out, out, b_out, 4096, 768, 768, 768, 768);
}

// round 8
// speedup vs baseline: 1.1116x; 1.0541x over previous
#include <cuda_runtime.h>
#include <cstdint>

#define EPSF 1e-6f

#define NP     1024
#define DIM    768
#define QK_LD  6144   /* q|k combined columns: 2 * 48 * 64 */
#define V_LD   3072

typedef unsigned long long u64;

// Packed f32x2 helpers (attention kernel)
#define FFMA2(d, a, b) \
    asm volatile("fma.rn.f32x2 %0, %1, %2, %0;" : "+l"(d) : "l"(a), "l"(b))
#define DUP2(d, s) \
    asm("mov.b64 %0, {%1, %1};" : "=l"(d) : "r"(__float_as_uint(s)))
#define UNPK2(lo, hi, d) \
    asm("mov.b64 {%0, %1}, %2;" : "=f"(lo), "=f"(hi) : "l"(d))

// tf32 split: x ~= hi + lo, both tf32-representable (3xTF32 trick)
__device__ __forceinline__ void tf32_split(float f, float& hi, float& lo) {
    uint32_t h, l;
    asm("cvt.rna.tf32.f32 %0, %1;" : "=r"(h) : "f"(f));
    float r = f - __uint_as_float(h);
    asm("cvt.rna.tf32.f32 %0, %1;" : "=r"(l) : "f"(r));
    hi = __uint_as_float(h);
    lo = __uint_as_float(l);
}

#define MMA_TF32(cc, a, b) \
    asm volatile("mma.sync.aligned.m16n8k8.row.col.f32.tf32.tf32.f32 " \
        "{%0,%1,%2,%3}, {%4,%5,%6,%7}, {%8,%9}, {%0,%1,%2,%3};" \
        : "+f"(cc[0]), "+f"(cc[1]), "+f"(cc[2]), "+f"(cc[3]) \
        : "r"(a[0]), "r"(a[1]), "r"(a[2]), "r"(a[3]), "r"(b[0]), "r"(b[1]))

// Scratch (device globals: allowed; no runtime allocation)
__device__ float g_qkbuf[NP * QK_LD];          // feature-mapped q|k, [n, col]
__device__ float g_qk2 [NP * QK_LD];           // q|k after graph mix
__device__ float g_v   [NP * V_LD];            // v, [n, col]
__device__ float g_attn[4 * NP * DIM];         // attention output [B*N, C]

// ---------------------------------------------------------------------------
// Tensor-core GEMM: 128x128 block tile, 8 warps (4m x 2n), warp tile 32x64,
// K-stage 16, mma.sync.m16n8k8.tf32 with 3xTF32 split (fp32-grade accuracy).
// TRANSA=false: A row-major [M,K].  TRANSA=true: op(A)=A^T with A [K,M].
// EPI 0: qkv scatter+relu+eps   EPI 1: C = F + 0.1*acc   EPI 2: C = acc + bias
// ---------------------------------------------------------------------------
template<bool TRANSA, int EPI>
__global__ __launch_bounds__(256, 1)
void tgemm_kernel(const float* __restrict__ A, const float* __restrict__ B,
                  float* __restrict__ C, const float* __restrict__ bias,
                  int M, int N, int K, int lda, int ldb)
{
    // k-major tiles, pad 136: fragment LDS bank = (8*tg + g) mod 32 -> conflict-free
    __shared__ float Ah[16][136], Al[16][136];
    __shared__ float Bh[16][136], Bl[16][136];

    const int tid  = threadIdx.x;
    const int lane = tid & 31;
    const int warp = tid >> 5;
    const int wm   = warp & 3;          // 0..3  (m)
    const int wn   = warp >> 2;         // 0..1  (n)
    const int g    = lane >> 2;         // 0..7
    const int tg   = lane & 3;          // 0..3
    const int m_base = blockIdx.y * 128;
    const int n_base = blockIdx.x * 128;

    float c[2][8][4];
    #pragma unroll
    for (int mt = 0; mt < 2; mt++)
        #pragma unroll
        for (int nt = 0; nt < 8; nt++)
            #pragma unroll
            for (int q = 0; q < 4; q++) c[mt][nt][q] = 0.f;

    for (int k0 = 0; k0 < K; k0 += 16) {
        // ---- load A tile -> Ah/Al (k-major [k][m]) ----
        if (!TRANSA) {
            const int row = tid >> 1, kg = (tid & 1) * 8;
            const float* ap = &A[(size_t)(m_base + row) * lda + k0 + kg];
            float4 v0 = *(const float4*)ap;
            float4 v1 = *(const float4*)(ap + 4);
            const float f[8] = {v0.x, v0.y, v0.z, v0.w, v1.x, v1.y, v1.z, v1.w};
            #pragma unroll
            for (int j = 0; j < 8; j++) {
                float h, l; tf32_split(f[j], h, l);
                Ah[kg + j][row] = h;
                Al[kg + j][row] = l;
            }
        } else {
            const int k = tid >> 4, m8 = (tid & 15) * 8;
            const float* ap = &A[(size_t)(k0 + k) * lda + m_base + m8];
            float4 v0 = *(const float4*)ap;
            float4 v1 = *(const float4*)(ap + 4);
            const float f[8] = {v0.x, v0.y, v0.z, v0.w, v1.x, v1.y, v1.z, v1.w};
            float h[8], l[8];
            #pragma unroll
            for (int j = 0; j < 8; j++) tf32_split(f[j], h[j], l[j]);
            *(float4*)&Ah[k][m8]   = make_float4(h[0], h[1], h[2], h[3]);
            *(float4*)&Ah[k][m8+4] = make_float4(h[4], h[5], h[6], h[7]);
            *(float4*)&Al[k][m8]   = make_float4(l[0], l[1], l[2], l[3]);
            *(float4*)&Al[k][m8+4] = make_float4(l[4], l[5], l[6], l[7]);
        }
        // ---- load B tile -> Bh/Bl (k-major [k][n]) ----
        {
            const int k = tid >> 4, n8 = (tid & 15) * 8;
            const float* bp = &B[(size_t)(k0 + k) * ldb + n_base + n8];
            float4 v0 = *(const float4*)bp;
            float4 v1 = *(const float4*)(bp + 4);
            const float f[8] = {v0.x, v0.y, v0.z, v0.w, v1.x, v1.y, v1.z, v1.w};
            float h[8], l[8];
            #pragma unroll
            for (int j = 0; j < 8; j++) tf32_split(f[j], h[j], l[j]);
            *(float4*)&Bh[k][n8]   = make_float4(h[0], h[1], h[2], h[3]);
            *(float4*)&Bh[k][n8+4] = make_float4(h[4], h[5], h[6], h[7]);
            *(float4*)&Bl[k][n8]   = make_float4(l[0], l[1], l[2], l[3]);
            *(float4*)&Bl[k][n8+4] = make_float4(l[4], l[5], l[6], l[7]);
        }
        __syncthreads();

        #pragma unroll
        for (int ks = 0; ks < 16; ks += 8) {
            uint32_t bh[8][2], bl[8][2];
            #pragma unroll
            for (int nt = 0; nt < 8; nt++) {
                const int cb = wn * 64 + nt * 8 + g;
                bh[nt][0] = __float_as_uint(Bh[ks + tg][cb]);
                bh[nt][1] = __float_as_uint(Bh[ks + tg + 4][cb]);
                bl[nt][0] = __float_as_uint(Bl[ks + tg][cb]);
                bl[nt][1] = __float_as_uint(Bl[ks + tg + 4][cb]);
            }
            #pragma unroll
            for (int mt = 0; mt < 2; mt++) {
                const int rb = wm * 32 + mt * 16;
                uint32_t ah[4], al[4];
                ah[0] = __float_as_uint(Ah[ks + tg][rb + g]);
                ah[1] = __float_as_uint(Ah[ks + tg][rb + g + 8]);
                ah[2] = __float_as_uint(Ah[ks + tg + 4][rb + g]);
                ah[3] = __float_as_uint(Ah[ks + tg + 4][rb + g + 8]);
                al[0] = __float_as_uint(Al[ks + tg][rb + g]);
                al[1] = __float_as_uint(Al[ks + tg][rb + g + 8]);
                al[2] = __float_as_uint(Al[ks + tg + 4][rb + g]);
                al[3] = __float_as_uint(Al[ks + tg + 4][rb + g + 8]);
                #pragma unroll
                for (int nt = 0; nt < 8; nt++) {
                    MMA_TF32(c[mt][nt], ah, bh[nt]);   // hi*hi
                    MMA_TF32(c[mt][nt], ah, bl[nt]);   // hi*lo
                    MMA_TF32(c[mt][nt], al, bh[nt]);   // lo*hi
                }
            }
        }
        __syncthreads();
    }

    // -------- epilogue (per-thread: rows r and r+8, col pair 2tg,2tg+1) -----
    #pragma unroll
    for (int mt = 0; mt < 2; mt++) {
        #pragma unroll
        for (int nt = 0; nt < 8; nt++) {
            const int row0 = m_base + wm * 32 + mt * 16 + g;
            const int col  = n_base + wn * 64 + nt * 8 + 2 * tg;
            #pragma unroll
            for (int h2 = 0; h2 < 2; h2++) {
                const int row = row0 + h2 * 8;
                float vx = c[mt][nt][h2 * 2 + 0];
                float vy = c[mt][nt][h2 * 2 + 1];
                if (EPI == 0) {
                    const int bb = row >> 10;
                    const int n  = row & 1023;
                    if (col < 1536) {
                        vx = fmaxf(vx, 0.f) + EPSF;
                        vy = fmaxf(vy, 0.f) + EPSF;
                        const int off = (col < 768) ? (bb * 768 + col)
                                                    : (3072 + bb * 768 + (col - 768));
                        *(float2*)&g_qkbuf[(size_t)n * QK_LD + off] = make_float2(vx, vy);
                    } else {
                        *(float2*)&g_v[(size_t)n * V_LD + bb * 768 + (col - 1536)] =
                            make_float2(vx, vy);
                    }
                } else if (EPI == 1) {
                    float2 f = *(const float2*)&g_qkbuf[(size_t)row * N + col];
                    *(float2*)&C[(size_t)row * N + col] =
                        make_float2(f.x + 0.1f * vx, f.y + 0.1f * vy);
                } else {
                    float2 bv = *(const float2*)&bias[col];
                    *(float2*)&C[(size_t)row * N + col] =
                        make_float2(vx + bv.x, vy + bv.y);
                }
            }
        }
    }
}

// ---------------------------------------------------------------------------
// Masked linear attention, flash-style, FFMA2 inner loops (unchanged, passing).
// grid = (16 n-tiles, 48 bh). block = 256 threads, 64x64 output tile.
// ---------------------------------------------------------------------------
#define ATTN_SMEM ((4 * 64 * 68 + 64 * 64) * 4)

__global__ __launch_bounds__(256)
void attn_kernel(const float* __restrict__ mask)
{
    extern __shared__ float sm[];
    float* Qs = sm;                 // [64][68]  Qs[d][n]
    float* Ks = Qs + 64*68;         // [64][68]  Ks[d][m]
    float* Ms = Ks + 64*68;         // [64][68]  Ms[n][m]
    float* Ps = Ms + 64*68;         // [64][68]  Ps[m][n]
    float* Vs = Ps + 64*68;         // [64][64]  Vs[m][d]

    const int tid = threadIdx.x;
    const int tr  = tid >> 4;
    const int tc  = tid & 15;
    const int n0  = blockIdx.x * 64;
    const int bh  = blockIdx.y;
    const int qoff = bh * 64;

    #pragma unroll
    for (int i = 0; i < 4; i++) {
        const int l = tid + i * 256;
        const int n = l >> 4, d4 = (l & 15) * 4;
        float4 v = *(const float4*)&g_qk2[(size_t)(n0 + n) * QK_LD + qoff + d4];
        Qs[(d4+0)*68 + n] = v.x; Qs[(d4+1)*68 + n] = v.y;
        Qs[(d4+2)*68 + n] = v.z; Qs[(d4+3)*68 + n] = v.w;
    }

    u64 acc2[4][2];
    #pragma unroll
    for (int i = 0; i < 4; i++) { acc2[i][0] = 0ull; acc2[i][1] = 0ull; }
    float rs[4] = {};

    for (int mt = 0; mt < 16; mt++) {
        const int m0 = mt * 64;
        __syncthreads();

        #pragma unroll
        for (int i = 0; i < 4; i++) {
            const int l = tid + i * 256;
            const int r = l >> 4, c4 = (l & 15) * 4;
            float4 kv = *(const float4*)&g_qk2[(size_t)(m0 + r) * QK_LD + 3072 + qoff + c4];
            Ks[(c4+0)*68 + r] = kv.x; Ks[(c4+1)*68 + r] = kv.y;
            Ks[(c4+2)*68 + r] = kv.z; Ks[(c4+3)*68 + r] = kv.w;
            *(float4*)&Vs[r*64 + c4] =
                *(const float4*)&g_v[(size_t)(m0 + r) * V_LD + qoff + c4];
            *(float4*)&Ms[r*68 + c4] =
                *(const float4*)&mask[(size_t)(n0 + r) * 1024 + m0 + c4];
        }
        __syncthreads();

        u64 s2[4][2];
        #pragma unroll
        for (int i = 0; i < 4; i++) { s2[i][0] = 0ull; s2[i][1] = 0ull; }
        #pragma unroll 8
        for (int d = 0; d < 64; d++) {
            float4 q = *(const float4*)&Qs[d*68 + tr*4];
            u64 k0p = *(const u64*)&Ks[d*68 + tc*4];
            u64 k1p = *(const u64*)&Ks[d*68 + tc*4 + 2];
            const float qa[4] = {q.x, q.y, q.z, q.w};
            #pragma unroll
            for (int i = 0; i < 4; i++) {
                u64 qd; DUP2(qd, qa[i]);
                FFMA2(s2[i][0], qd, k0p);
                FFMA2(s2[i][1], qd, k1p);
            }
        }
        #pragma unroll
        for (int i = 0; i < 4; i++) {
            float s[4];
            UNPK2(s[0], s[1], s2[i][0]);
            UNPK2(s[2], s[3], s2[i][1]);
            #pragma unroll
            for (int j = 0; j < 4; j++)
                Ps[(tc*4+j)*68 + tr*4+i] = s[j] * Ms[(tr*4+i)*68 + tc*4+j];
        }
        __syncthreads();

        #pragma unroll 8
        for (int m = 0; m < 64; m++) {
            float4 p = *(const float4*)&Ps[m*68 + tr*4];
            u64 v0p = *(const u64*)&Vs[m*64 + tc*4];
            u64 v1p = *(const u64*)&Vs[m*64 + tc*4 + 2];
            const float pa[4] = {p.x, p.y, p.z, p.w};
            #pragma unroll
            for (int i = 0; i < 4; i++) {
                rs[i] += pa[i];
                u64 pd; DUP2(pd, pa[i]);
                FFMA2(acc2[i][0], pd, v0p);
                FFMA2(acc2[i][1], pd, v1p);
            }
        }
    }

    const int b = bh / 12, h = bh % 12;
    #pragma unroll
    for (int i = 0; i < 4; i++) {
        const float z = 1.f / (rs[i] + EPSF);
        float a[4];
        UNPK2(a[0], a[1], acc2[i][0]);
        UNPK2(a[2], a[3], acc2[i][1]);
        const size_t row = (size_t)(b * 1024 + n0 + tr*4 + i);
        float4 o = make_float4(a[0]*z, a[1]*z, a[2]*z, a[3]*z);
        *(float4*)&g_attn[row * 768 + h*64 + tc*4] = o;
    }
}

// ---------------------------------------------------------------------------

extern "C" void kernel_launch(void* const* d_in, const int* in_sizes, int n_in,
                              void* d_out, int out_size)
{
    (void)in_sizes; (void)n_in; (void)out_size;
    const float* x     = (const float*)d_in[0];   // [4,1024,768]
    const float* W_qkv = (const float*)d_in[1];   // [768,2304]
    const float* W_out = (const float*)d_in[2];   // [768,768]
    const float* b_out = (const float*)d_in[3];   // [768]
    const float* mask  = (const float*)d_in[4];   // [1024,1024]
    float* out = (float*)d_out;                   // [4,1024,768]

    float *p_qkbuf = nullptr, *p_qk2 = nullptr, *p_attn = nullptr;
    cudaGetSymbolAddress((void**)&p_qkbuf, g_qkbuf);
    cudaGetSymbolAddress((void**)&p_qk2,  g_qk2);
    cudaGetSymbolAddress((void**)&p_attn, g_attn);

    cudaFuncSetAttribute(attn_kernel,
                         cudaFuncAttributeMaxDynamicSharedMemorySize, ATTN_SMEM);

    dim3 blk(256);

    // 1) QKV GEMM: [4096,768] @ [768,2304] -> relu/eps scatter into g_qkbuf / g_v
    tgemm_kernel<false, 0><<<dim3(2304/128, 4096/128), blk>>>(
        x, W_qkv, nullptr, nullptr, 4096, 2304, 768, 768, 2304);

    // 2) Graph mix: g_qk2 = F + 0.1 * (mask^T @ F), F = g_qkbuf [1024,6144]
    tgemm_kernel<true, 1><<<dim3(6144/128, 1024/128), blk>>>(
        mask, p_qkbuf, p_qk2, nullptr, 1024, 6144, 1024, 1024, QK_LD);

    // 3) Masked linear attention -> g_attn [4096,768]
    attn_kernel<<<dim3(16, 48), blk, ATTN_SMEM>>>(mask);

    // 4) Output projection: [4096,768] @ [768,768] + b_out -> d_out
    tgemm_kernel<false, 2><<<dim3(768/128, 4096/128), blk>>>(
        p_attn, W_out, out, b_out, 4096, 768, 768, 768, 768);
}

// round 11
// speedup vs baseline: 1.2411x; 1.1165x over previous
#include <cuda_runtime.h>
#include <cstdint>

#define EPSF 1e-6f

#define NP     1024
#define DIM    768
#define QK_LD  6144   /* q|k combined columns: 2 * 48 * 64 */
#define V_LD   3072

typedef unsigned long long u64;

// Packed f32x2 helpers (attention kernel)
#define FFMA2(d, a, b) \
    asm volatile("fma.rn.f32x2 %0, %1, %2, %0;" : "+l"(d) : "l"(a), "l"(b))
#define DUP2(d, s) \
    asm("mov.b64 %0, {%1, %1};" : "=l"(d) : "r"(__float_as_uint(s)))
#define UNPK2(lo, hi, d) \
    asm("mov.b64 {%0, %1}, %2;" : "=f"(lo), "=f"(hi) : "l"(d))

// tf32 split: x ~= hi + lo, both tf32-representable (3xTF32 trick)
__device__ __forceinline__ void tf32_split(float f, float& hi, float& lo) {
    uint32_t h, l;
    asm("cvt.rna.tf32.f32 %0, %1;" : "=r"(h) : "f"(f));
    float r = f - __uint_as_float(h);
    asm("cvt.rna.tf32.f32 %0, %1;" : "=r"(l) : "f"(r));
    hi = __uint_as_float(h);
    lo = __uint_as_float(l);
}

#define MMA_TF32(cc, a, b) \
    asm volatile("mma.sync.aligned.m16n8k8.row.col.f32.tf32.tf32.f32 " \
        "{%0,%1,%2,%3}, {%4,%5,%6,%7}, {%8,%9}, {%0,%1,%2,%3};" \
        : "+f"(cc[0]), "+f"(cc[1]), "+f"(cc[2]), "+f"(cc[3]) \
        : "r"(a[0]), "r"(a[1]), "r"(a[2]), "r"(a[3]), "r"(b[0]), "r"(b[1]))

// Scratch (device globals: allowed; no runtime allocation)
__device__ float g_qkbuf[NP * QK_LD];          // feature-mapped q|k, [n, col]
__device__ float g_qk2 [NP * QK_LD];           // q|k after graph mix
__device__ float g_v   [NP * V_LD];            // v, [n, col]
__device__ float g_attn[4 * NP * DIM];         // attention output [B*N, C]

// ---------------------------------------------------------------------------
// Tensor-core GEMM: 128x128 block tile, 8 warps (4m x 2n), warp tile 32x64,
// K-stage 16, mma.m16n8k8.tf32 with 3xTF32 split, 2-stage smem pipeline.
// TRANSA=false: A row-major [M,K].  TRANSA=true: op(A)=A^T with A [K,M].
// EPI 0: qkv scatter+relu+eps   EPI 1: C = F + 0.1*acc   EPI 2: C = acc + bias
// ---------------------------------------------------------------------------
#define TS      (16 * 136)              /* one [16][136] tile   */
#define GEMM_SMEM (2 * 4 * TS * 4)      /* 2 stages x {Ah,Al,Bh,Bl} */

template<bool TRANSA, int EPI>
__global__ __launch_bounds__(256, 1)
void tgemm_kernel(const float* __restrict__ A, const float* __restrict__ B,
                  float* __restrict__ C, const float* __restrict__ bias,
                  int M, int N, int K, int lda, int ldb)
{
    extern __shared__ float sm_[];

    const int tid  = threadIdx.x;
    const int lane = tid & 31;
    const int warp = tid >> 5;
    const int wm   = warp & 3;          // 0..3  (m)
    const int wn   = warp >> 2;         // 0..1  (n)
    const int g    = lane >> 2;         // 0..7
    const int tg   = lane & 3;          // 0..3
    const int m_base = blockIdx.y * 128;
    const int n_base = blockIdx.x * 128;

    // per-thread global load coordinates (fixed across k-tiles)
    const int a_row = TRANSA ? (tid >> 4)        : (tid >> 1);
    const int a_off = TRANSA ? ((tid & 15) * 8)  : ((tid & 1) * 8);
    const int b_k   = tid >> 4;
    const int b_n8  = (tid & 15) * 8;

    float c[2][8][4];
    #pragma unroll
    for (int mt = 0; mt < 2; mt++)
        #pragma unroll
        for (int nt = 0; nt < 8; nt++)
            #pragma unroll
            for (int q = 0; q < 4; q++) c[mt][nt][q] = 0.f;

    float4 ra0, ra1, rb0, rb1;

    // ---- load tile k0 into registers ----
    auto load_regs = [&](int k0) {
        const float* ap = TRANSA
            ? &A[(size_t)(k0 + a_row) * lda + m_base + a_off]
            : &A[(size_t)(m_base + a_row) * lda + k0 + a_off];
        ra0 = *(const float4*)ap;
        ra1 = *(const float4*)(ap + 4);
        const float* bp = &B[(size_t)(k0 + b_k) * ldb + n_base + b_n8];
        rb0 = *(const float4*)bp;
        rb1 = *(const float4*)(bp + 4);
    };

    // ---- split registers and store into smem stage ----
    auto store_stage = [&](float* base) {
        float* Ah = base;
        float* Al = base + TS;
        float* Bh = base + 2 * TS;
        float* Bl = base + 3 * TS;
        const float fa[8] = {ra0.x, ra0.y, ra0.z, ra0.w, ra1.x, ra1.y, ra1.z, ra1.w};
        if (!TRANSA) {
            #pragma unroll
            for (int j = 0; j < 8; j++) {
                float h, l; tf32_split(fa[j], h, l);
                Ah[(a_off + j) * 136 + a_row] = h;
                Al[(a_off + j) * 136 + a_row] = l;
            }
        } else {
            float h[8], l[8];
            #pragma unroll
            for (int j = 0; j < 8; j++) tf32_split(fa[j], h[j], l[j]);
            *(float4*)&Ah[a_row * 136 + a_off]     = make_float4(h[0], h[1], h[2], h[3]);
            *(float4*)&Ah[a_row * 136 + a_off + 4] = make_float4(h[4], h[5], h[6], h[7]);
            *(float4*)&Al[a_row * 136 + a_off]     = make_float4(l[0], l[1], l[2], l[3]);
            *(float4*)&Al[a_row * 136 + a_off + 4] = make_float4(l[4], l[5], l[6], l[7]);
        }
        {
            const float fb[8] = {rb0.x, rb0.y, rb0.z, rb0.w, rb1.x, rb1.y, rb1.z, rb1.w};
            float h[8], l[8];
            #pragma unroll
            for (int j = 0; j < 8; j++) tf32_split(fb[j], h[j], l[j]);
            *(float4*)&Bh[b_k * 136 + b_n8]     = make_float4(h[0], h[1], h[2], h[3]);
            *(float4*)&Bh[b_k * 136 + b_n8 + 4] = make_float4(h[4], h[5], h[6], h[7]);
            *(float4*)&Bl[b_k * 136 + b_n8]     = make_float4(l[0], l[1], l[2], l[3]);
            *(float4*)&Bl[b_k * 136 + b_n8 + 4] = make_float4(l[4], l[5], l[6], l[7]);
        }
    };

    const int nk = K >> 4;

    // prologue: fill stage 0
    load_regs(0);
    store_stage(sm_);

    for (int kt = 0; kt < nk; kt++) {
        __syncthreads();                 // stage kt%2 ready; stage (kt+1)%2 free
        if (kt + 1 < nk)
            load_regs((kt + 1) << 4);    // global loads in flight during MMA

        float* base = sm_ + (kt & 1) * 4 * TS;
        const float* Ah = base;
        const float* Al = base + TS;
        const float* Bh = base + 2 * TS;
        const float* Bl = base + 3 * TS;

        #pragma unroll
        for (int ks = 0; ks < 16; ks += 8) {
            uint32_t bh[8][2], bl[8][2];
            #pragma unroll
            for (int nt = 0; nt < 8; nt++) {
                const int cb = wn * 64 + nt * 8 + g;
                bh[nt][0] = __float_as_uint(Bh[(ks + tg) * 136 + cb]);
                bh[nt][1] = __float_as_uint(Bh[(ks + tg + 4) * 136 + cb]);
                bl[nt][0] = __float_as_uint(Bl[(ks + tg) * 136 + cb]);
                bl[nt][1] = __float_as_uint(Bl[(ks + tg + 4) * 136 + cb]);
            }
            #pragma unroll
            for (int mt = 0; mt < 2; mt++) {
                const int rb = wm * 32 + mt * 16;
                uint32_t ah[4], al[4];
                ah[0] = __float_as_uint(Ah[(ks + tg) * 136 + rb + g]);
                ah[1] = __float_as_uint(Ah[(ks + tg) * 136 + rb + g + 8]);
                ah[2] = __float_as_uint(Ah[(ks + tg + 4) * 136 + rb + g]);
                ah[3] = __float_as_uint(Ah[(ks + tg + 4) * 136 + rb + g + 8]);
                al[0] = __float_as_uint(Al[(ks + tg) * 136 + rb + g]);
                al[1] = __float_as_uint(Al[(ks + tg) * 136 + rb + g + 8]);
                al[2] = __float_as_uint(Al[(ks + tg + 4) * 136 + rb + g]);
                al[3] = __float_as_uint(Al[(ks + tg + 4) * 136 + rb + g + 8]);
                #pragma unroll
                for (int nt = 0; nt < 8; nt++) {
                    MMA_TF32(c[mt][nt], ah, bh[nt]);   // hi*hi
                    MMA_TF32(c[mt][nt], ah, bl[nt]);   // hi*lo
                    MMA_TF32(c[mt][nt], al, bh[nt]);   // lo*hi
                }
            }
        }

        if (kt + 1 < nk)
            store_stage(sm_ + ((kt + 1) & 1) * 4 * TS);
    }

    // -------- epilogue (per-thread: rows r and r+8, col pair 2tg,2tg+1) -----
    #pragma unroll
    for (int mt = 0; mt < 2; mt++) {
        #pragma unroll
        for (int nt = 0; nt < 8; nt++) {
            const int row0 = m_base + wm * 32 + mt * 16 + g;
            const int col  = n_base + wn * 64 + nt * 8 + 2 * tg;
            #pragma unroll
            for (int h2 = 0; h2 < 2; h2++) {
                const int row = row0 + h2 * 8;
                float vx = c[mt][nt][h2 * 2 + 0];
                float vy = c[mt][nt][h2 * 2 + 1];
                if (EPI == 0) {
                    const int bb = row >> 10;
                    const int n  = row & 1023;
                    if (col < 1536) {
                        vx = fmaxf(vx, 0.f) + EPSF;
                        vy = fmaxf(vy, 0.f) + EPSF;
                        const int off = (col < 768) ? (bb * 768 + col)
                                                    : (3072 + bb * 768 + (col - 768));
                        *(float2*)&g_qkbuf[(size_t)n * QK_LD + off] = make_float2(vx, vy);
                    } else {
                        *(float2*)&g_v[(size_t)n * V_LD + bb * 768 + (col - 1536)] =
                            make_float2(vx, vy);
                    }
                } else if (EPI == 1) {
                    float2 f = *(const float2*)&g_qkbuf[(size_t)row * N + col];
                    *(float2*)&C[(size_t)row * N + col] =
                        make_float2(f.x + 0.1f * vx, f.y + 0.1f * vy);
                } else {
                    float2 bv = *(const float2*)&bias[col];
                    *(float2*)&C[(size_t)row * N + col] =
                        make_float2(vx + bv.x, vy + bv.y);
                }
            }
        }
    }
}

// ---------------------------------------------------------------------------
// Masked linear attention, flash-style, FFMA2 inner loops (unchanged, passing).
// grid = (16 n-tiles, 48 bh). block = 256 threads, 64x64 output tile.
// ---------------------------------------------------------------------------
#define ATTN_SMEM ((4 * 64 * 68 + 64 * 64) * 4)

__global__ __launch_bounds__(256)
void attn_kernel(const float* __restrict__ mask)
{
    extern __shared__ float sm[];
    float* Qs = sm;                 // [64][68]  Qs[d][n]
    float* Ks = Qs + 64*68;         // [64][68]  Ks[d][m]
    float* Ms = Ks + 64*68;         // [64][68]  Ms[n][m]
    float* Ps = Ms + 64*68;         // [64][68]  Ps[m][n]
    float* Vs = Ps + 64*68;         // [64][64]  Vs[m][d]

    const int tid = threadIdx.x;
    const int tr  = tid >> 4;
    const int tc  = tid & 15;
    const int n0  = blockIdx.x * 64;
    const int bh  = blockIdx.y;
    const int qoff = bh * 64;

    #pragma unroll
    for (int i = 0; i < 4; i++) {
        const int l = tid + i * 256;
        const int n = l >> 4, d4 = (l & 15) * 4;
        float4 v = *(const float4*)&g_qk2[(size_t)(n0 + n) * QK_LD + qoff + d4];
        Qs[(d4+0)*68 + n] = v.x; Qs[(d4+1)*68 + n] = v.y;
        Qs[(d4+2)*68 + n] = v.z; Qs[(d4+3)*68 + n] = v.w;
    }

    u64 acc2[4][2];
    #pragma unroll
    for (int i = 0; i < 4; i++) { acc2[i][0] = 0ull; acc2[i][1] = 0ull; }
    float rs[4] = {};

    for (int mt = 0; mt < 16; mt++) {
        const int m0 = mt * 64;
        __syncthreads();

        #pragma unroll
        for (int i = 0; i < 4; i++) {
            const int l = tid + i * 256;
            const int r = l >> 4, c4 = (l & 15) * 4;
            float4 kv = *(const float4*)&g_qk2[(size_t)(m0 + r) * QK_LD + 3072 + qoff + c4];
            Ks[(c4+0)*68 + r] = kv.x; Ks[(c4+1)*68 + r] = kv.y;
            Ks[(c4+2)*68 + r] = kv.z; Ks[(c4+3)*68 + r] = kv.w;
            *(float4*)&Vs[r*64 + c4] =
                *(const float4*)&g_v[(size_t)(m0 + r) * V_LD + qoff + c4];
            *(float4*)&Ms[r*68 + c4] =
                *(const float4*)&mask[(size_t)(n0 + r) * 1024 + m0 + c4];
        }
        __syncthreads();

        u64 s2[4][2];
        #pragma unroll
        for (int i = 0; i < 4; i++) { s2[i][0] = 0ull; s2[i][1] = 0ull; }
        #pragma unroll 8
        for (int d = 0; d < 64; d++) {
            float4 q = *(const float4*)&Qs[d*68 + tr*4];
            u64 k0p = *(const u64*)&Ks[d*68 + tc*4];
            u64 k1p = *(const u64*)&Ks[d*68 + tc*4 + 2];
            const float qa[4] = {q.x, q.y, q.z, q.w};
            #pragma unroll
            for (int i = 0; i < 4; i++) {
                u64 qd; DUP2(qd, qa[i]);
                FFMA2(s2[i][0], qd, k0p);
                FFMA2(s2[i][1], qd, k1p);
            }
        }
        #pragma unroll
        for (int i = 0; i < 4; i++) {
            float s[4];
            UNPK2(s[0], s[1], s2[i][0]);
            UNPK2(s[2], s[3], s2[i][1]);
            #pragma unroll
            for (int j = 0; j < 4; j++)
                Ps[(tc*4+j)*68 + tr*4+i] = s[j] * Ms[(tr*4+i)*68 + tc*4+j];
        }
        __syncthreads();

        #pragma unroll 8
        for (int m = 0; m < 64; m++) {
            float4 p = *(const float4*)&Ps[m*68 + tr*4];
            u64 v0p = *(const u64*)&Vs[m*64 + tc*4];
            u64 v1p = *(const u64*)&Vs[m*64 + tc*4 + 2];
            const float pa[4] = {p.x, p.y, p.z, p.w};
            #pragma unroll
            for (int i = 0; i < 4; i++) {
                rs[i] += pa[i];
                u64 pd; DUP2(pd, pa[i]);
                FFMA2(acc2[i][0], pd, v0p);
                FFMA2(acc2[i][1], pd, v1p);
            }
        }
    }

    const int b = bh / 12, h = bh % 12;
    #pragma unroll
    for (int i = 0; i < 4; i++) {
        const float z = 1.f / (rs[i] + EPSF);
        float a[4];
        UNPK2(a[0], a[1], acc2[i][0]);
        UNPK2(a[2], a[3], acc2[i][1]);
        const size_t row = (size_t)(b * 1024 + n0 + tr*4 + i);
        float4 o = make_float4(a[0]*z, a[1]*z, a[2]*z, a[3]*z);
        *(float4*)&g_attn[row * 768 + h*64 + tc*4] = o;
    }
}

// ---------------------------------------------------------------------------

extern "C" void kernel_launch(void* const* d_in, const int* in_sizes, int n_in,
                              void* d_out, int out_size)
{
    (void)in_sizes; (void)n_in; (void)out_size;
    const float* x     = (const float*)d_in[0];   // [4,1024,768]
    const float* W_qkv = (const float*)d_in[1];   // [768,2304]
    const float* W_out = (const float*)d_in[2];   // [768,768]
    const float* b_out = (const float*)d_in[3];   // [768]
    const float* mask  = (const float*)d_in[4];   // [1024,1024]
    float* out = (float*)d_out;                   // [4,1024,768]

    float *p_qkbuf = nullptr, *p_qk2 = nullptr, *p_attn = nullptr;
    cudaGetSymbolAddress((void**)&p_qkbuf, g_qkbuf);
    cudaGetSymbolAddress((void**)&p_qk2,  g_qk2);
    cudaGetSymbolAddress((void**)&p_attn, g_attn);

    cudaFuncSetAttribute(attn_kernel,
                         cudaFuncAttributeMaxDynamicSharedMemorySize, ATTN_SMEM);
    cudaFuncSetAttribute(tgemm_kernel<false, 0>,
                         cudaFuncAttributeMaxDynamicSharedMemorySize, GEMM_SMEM);
    cudaFuncSetAttribute(tgemm_kernel<true, 1>,
                         cudaFuncAttributeMaxDynamicSharedMemorySize, GEMM_SMEM);
    cudaFuncSetAttribute(tgemm_kernel<false, 2>,
                         cudaFuncAttributeMaxDynamicSharedMemorySize, GEMM_SMEM);

    dim3 blk(256);

    // 1) QKV GEMM: [4096,768] @ [768,2304] -> relu/eps scatter into g_qkbuf / g_v
    tgemm_kernel<false, 0><<<dim3(2304/128, 4096/128), blk, GEMM_SMEM>>>(
        x, W_qkv, nullptr, nullptr, 4096, 2304, 768, 768, 2304);

    // 2) Graph mix: g_qk2 = F + 0.1 * (mask^T @ F), F = g_qkbuf [1024,6144]
    tgemm_kernel<true, 1><<<dim3(6144/128, 1024/128), blk, GEMM_SMEM>>>(
        mask, p_qkbuf, p_qk2, nullptr, 1024, 6144, 1024, 1024, QK_LD);

    // 3) Masked linear attention -> g_attn [4096,768]
    attn_kernel<<<dim3(16, 48), blk, ATTN_SMEM>>>(mask);

    // 4) Output projection: [4096,768] @ [768,768] + b_out -> d_out
    tgemm_kernel<false, 2><<<dim3(768/128, 4096/128), blk, GEMM_SMEM>>>(
        p_attn, W_out, out, b_out, 4096, 768, 768, 768, 768);
}